// round 10
// baseline (speedup 1.0000x reference)
#include <cuda_runtime.h>
#include <math.h>

#define DEPTH 2
#define NQ 4
#define M_CH 512
#define B_SZ 128
#define NSL 8              // 4-row slices per image
#define NPAIR 136          // symmetric 16x16 pairs

// Pooling partials: [b][slice][side][m] -> 2 MB (L2-resident)
__device__ float g_part[B_SZ * NSL * 2 * M_CH];
// Symmetric quadratic-form matrices, transposed: [pair e][m] -> 278 KB
__device__ float g_M[NPAIR * M_CH];

// ---- Kernel M: build M_m = Re(U† Z0 U) for all channels. CTA = 8 channels. ----
__global__ __launch_bounds__(128) void mbuild_kernel(const float* __restrict__ w) {
    const int cta   = blockIdx.x;        // 0..63
    const int t     = threadIdx.x;       // 0..127
    const int mbase = cta * 8;

    __shared__ float sg[8][8][8];        // [ch][step][gate floats]
    __shared__ float sur[8][16][17];     // [ch][x][col] pitch 17
    __shared__ float sui[8][16][17];

    // Phase 1: gates (64 threads: one (ch, step) each)
    if (t < 64) {
        const int ch = t >> 3, step = t & 7;
        const float* wp = w + (size_t)(mbase + ch) * (DEPTH * NQ * 3) + step * 3;
        float phi = wp[0], th = wp[1], om = wp[2];
        float st, ct; sincosf(0.5f * th,         &st, &ct);
        float sp, cp; sincosf(0.5f * (phi + om), &sp, &cp);
        float sm, cm; sincosf(0.5f * (phi - om), &sm, &cm);
        float* g = sg[ch][step];
        g[0] =  cp * ct;  g[1] = -sp * ct;   // g00
        g[2] = -cm * st;  g[3] = -sm * st;   // g01
        g[4] =  cm * st;  g[5] = -sm * st;   // g10
        g[6] =  cp * ct;  g[7] =  sp * ct;   // g11
    }
    __syncthreads();

    // Phase 2: evolve basis column. thread = (ch = t>>4, col = t&15)
    {
        const int ch = t >> 4, col = t & 15;
        float re[16], im[16];
        #pragma unroll
        for (int x = 0; x < 16; x++) { re[x] = (x == col) ? 1.f : 0.f; im[x] = 0.f; }

        const int PERM[16] = {0, 1, 3, 2, 6, 7, 5, 4, 12, 13, 15, 14, 10, 11, 9, 8};
        #pragma unroll
        for (int step = 0; step < DEPTH * NQ; step++) {
            const float* g = sg[ch][step];
            float gAx = g[0], gAy = g[1], gAz = g[2], gAw = g[3];
            float gBx = g[4], gBy = g[5], gBz = g[6], gBw = g[7];
            const int mask = 8 >> (step & 3);
            #pragma unroll
            for (int i = 0; i < 16; i++) {
                if (i & mask) continue;
                const int j = i | mask;
                float ar = re[i], ai = im[i], br = re[j], bi = im[j];
                re[i] = gAx * ar - gAy * ai + gAz * br - gAw * bi;
                im[i] = gAx * ai + gAy * ar + gAz * bi + gAw * br;
                re[j] = gBx * ar - gBy * ai + gBz * br - gBw * bi;
                im[j] = gBx * ai + gBy * ar + gBz * bi + gBw * br;
            }
            if ((step & 3) == 3) {
                float tr[16], ti[16];
                #pragma unroll
                for (int x = 0; x < 16; x++) { tr[PERM[x]] = re[x]; ti[PERM[x]] = im[x]; }
                #pragma unroll
                for (int x = 0; x < 16; x++) { re[x] = tr[x]; im[x] = ti[x]; }
            }
        }
        #pragma unroll
        for (int x = 0; x < 16; x++) { sur[ch][x][col] = re[x]; sui[ch][x][col] = im[x]; }
    }
    __syncthreads();

    // Phase 3: M rows. thread = (ch = t>>4, i = t&15); entries j >= i.
    {
        const int ch = t >> 4, i = t & 15;
        const int m  = mbase + ch;
        float uri[16], uii[16];
        #pragma unroll
        for (int x = 0; x < 16; x++) { uri[x] = sur[ch][x][i]; uii[x] = sui[ch][x][i]; }
        int e = i * 16 - (i * (i - 1)) / 2;     // row offset in pair list
        for (int j = i; j < 16; j++, e++) {
            float acc = 0.f;
            #pragma unroll
            for (int x = 0; x < 8; x++)
                acc += uri[x] * sur[ch][x][j] + uii[x] * sui[ch][x][j];
            #pragma unroll
            for (int x = 8; x < 16; x++)
                acc -= uri[x] * sur[ch][x][j] + uii[x] * sui[ch][x][j];
            g_M[e * M_CH + m] = acc;
        }
    }
}

// ---- Kernel P: streaming pool (byte-identical to proven 38us version). ----
__global__ __launch_bounds__(512) void pool_kernel(const float* __restrict__ in) {
    const int bid = blockIdx.x;            // 0..1023
    const int t   = threadIdx.x;           // 0..511
    const int b     = bid >> 3;
    const int slice = bid & (NSL - 1);
    const int rs    = t >> 7;
    const int m4    = t & 127;
    const int row   = slice * 4 + rs;

    const float4* rp = (const float4*)in
                     + ((size_t)b * 1024 + (size_t)row * 32) * 128 + m4;
    float4 sL = make_float4(0.f, 0.f, 0.f, 0.f);
    float4 sR = make_float4(0.f, 0.f, 0.f, 0.f);
    #pragma unroll
    for (int c = 0; c < 16; c++) {
        float4 v = __ldcs(rp + c * 128);
        sL.x += v.x; sL.y += v.y; sL.z += v.z; sL.w += v.w;
    }
    #pragma unroll
    for (int c = 16; c < 32; c++) {
        float4 v = __ldcs(rp + c * 128);
        sR.x += v.x; sR.y += v.y; sR.z += v.z; sR.w += v.w;
    }

    __shared__ float4 red[512 * 2];
    red[t * 2]     = sL;
    red[t * 2 + 1] = sR;
    __syncthreads();
    if (t < 256) {
        float4 a = red[t * 2],     b4 = red[(t + 256) * 2];
        float4 c = red[t * 2 + 1], d4 = red[(t + 256) * 2 + 1];
        a.x += b4.x; a.y += b4.y; a.z += b4.z; a.w += b4.w;
        c.x += d4.x; c.y += d4.y; c.z += d4.z; c.w += d4.w;
        red[t * 2]     = a;
        red[t * 2 + 1] = c;
    }
    __syncthreads();
    if (t < 128) {
        float4 a = red[t * 2],     b4 = red[(t + 128) * 2];
        float4 c = red[t * 2 + 1], d4 = red[(t + 128) * 2 + 1];
        a.x += b4.x; a.y += b4.y; a.z += b4.z; a.w += b4.w;
        c.x += d4.x; c.y += d4.y; c.z += d4.z; c.w += d4.w;
        float4* p = (float4*)g_part + ((size_t)(b * NSL + slice) * 2) * 128 + t;
        p[0]   = a;
        p[128] = c;
    }
}

__device__ __forceinline__ float fast_tanh(float x) {
    return __fdividef(2.f, 1.f + __expf(-2.f * x)) - 1.f;
}

// ---- Kernel Q: quadratic form z = psi^T M psi per (b, m). ----
__global__ __launch_bounds__(256) void qf_kernel(float* __restrict__ out) {
    const int b = blockIdx.x >> 1;                       // 0..127
    const int m = ((blockIdx.x & 1) << 8) + threadIdx.x; // 0..511

    // partials: [b][slice(8)][side(2)][m]; slices 0..3 top, 4..7 bottom
    const float* p = g_part + (size_t)b * (NSL * 2 * M_CH) + m;
    float v[16];
    #pragma unroll
    for (int s = 0; s < 16; s++) v[s] = p[s * M_CH];
    float a00 = 0.f, a01 = 0.f, a10 = 0.f, a11 = 0.f;
    #pragma unroll
    for (int s = 0; s < 4; s++) { a00 += v[s * 2]; a01 += v[s * 2 + 1]; }
    #pragma unroll
    for (int s = 4; s < 8; s++) { a10 += v[s * 2]; a11 += v[s * 2 + 1]; }

    const float PI = 3.14159265358979f;
    const float inv = 1.f / 256.f;
    float ang0 = fast_tanh(a00 * inv) * PI;
    float ang1 = fast_tanh(a01 * inv) * PI;
    float ang2 = fast_tanh(a10 * inv) * PI;
    float ang3 = fast_tanh(a11 * inv) * PI;

    float s0, c0, s1, c1, s2, c2, s3, c3;
    __sincosf(0.5f * ang0, &s0, &c0);   // |arg| <= pi/2
    __sincosf(0.5f * ang1, &s1, &c1);
    __sincosf(0.5f * ang2, &s2, &c2);
    __sincosf(0.5f * ang3, &s3, &c3);

    float psi[16];
    {
        float p0[2] = {c0, s0}, p1[2] = {c1, s1}, p2_[2] = {c2, s2}, p3[2] = {c3, s3};
        #pragma unroll
        for (int x = 0; x < 16; x++)
            psi[x] = p0[(x >> 3) & 1] * p1[(x >> 2) & 1] * p2_[(x >> 1) & 1] * p3[x & 1];
    }

    // z = sum over pairs: diag psi_i^2 * M_ii + offdiag 2 psi_i psi_j * M_ij
    const float* Mp = g_M + m;
    float z0 = 0.f, z1 = 0.f, z2 = 0.f, z3 = 0.f;
    int e = 0;
    #pragma unroll
    for (int i = 0; i < 16; i++) {
        #pragma unroll
        for (int j = i; j < 16; j++) {
            float c = psi[i] * psi[j];
            if (j != i) c += c;
            float Mv = __ldg(Mp + e * M_CH);
            switch (e & 3) {
                case 0: z0 = fmaf(Mv, c, z0); break;
                case 1: z1 = fmaf(Mv, c, z1); break;
                case 2: z2 = fmaf(Mv, c, z2); break;
                default: z3 = fmaf(Mv, c, z3); break;
            }
            e++;
        }
    }
    out[(size_t)b * M_CH + m] = (z0 + z1) + (z2 + z3);
}

extern "C" void kernel_launch(void* const* d_in, const int* in_sizes, int n_in,
                              void* d_out, int out_size) {
    const float* in = (const float*)d_in[0];
    const float* w  = (const float*)d_in[1];
    if (n_in >= 2 && in_sizes[0] < in_sizes[1]) {
        const float* t = in; in = w; w = t;
    }
    mbuild_kernel<<<64, 128>>>(w);
    pool_kernel<<<B_SZ * NSL, 512>>>(in);
    qf_kernel<<<B_SZ * 2, 256>>>((float*)d_out);
}

// round 11
// speedup vs baseline: 1.0448x; 1.0448x over previous
#include <cuda_runtime.h>
#include <math.h>

#define DEPTH 2
#define NQ 4
#define M_CH 512
#define B_SZ 128
#define NSL 8              // 4-row slices per image
#define NPAIR 136          // symmetric 16x16 pairs (x2 folded into off-diag)
#define MBLK 64            // channels per qf CTA

// Pooling partials: [b][slice][side][m] -> 2 MB (L2-resident)
__device__ float g_part[B_SZ * NSL * 2 * M_CH];
// Quadratic-form matrices (2x folded off-diag), transposed: [pair e][m]
__device__ float g_M[NPAIR * M_CH];

// ---- Kernel M: build M'_m. CTA = 4 channels x 16 basis cols = 64 threads. ----
__global__ __launch_bounds__(64) void mbuild_kernel(const float* __restrict__ w) {
    const int t   = threadIdx.x;         // 0..63
    const int ch  = t >> 4;              // 0..3
    const int col = t & 15;              // basis column
    const int m   = blockIdx.x * 4 + ch;

    __shared__ float sur[4][16][17];     // [ch][x][col] pitch 17
    __shared__ float sui[4][16][17];

    // evolve basis column `col` through all 8 Rot steps + CNOT cascades
    float re[16], im[16];
    #pragma unroll
    for (int x = 0; x < 16; x++) { re[x] = (x == col) ? 1.f : 0.f; im[x] = 0.f; }

    const int PERM[16] = {0, 1, 3, 2, 6, 7, 5, 4, 12, 13, 15, 14, 10, 11, 9, 8};
    const float* wm = w + (size_t)m * (DEPTH * NQ * 3);

    #pragma unroll
    for (int step = 0; step < DEPTH * NQ; step++) {
        const float* wp = wm + step * 3;
        float phi = wp[0], th = wp[1], om = wp[2];
        float st, ct; __sincosf(0.5f * th,         &st, &ct);
        float sp, cp; __sincosf(0.5f * (phi + om), &sp, &cp);
        float sm, cm; __sincosf(0.5f * (phi - om), &sm, &cm);
        float gAx =  cp * ct, gAy = -sp * ct;   // g00
        float gAz = -cm * st, gAw = -sm * st;   // g01
        float gBx =  cm * st, gBy = -sm * st;   // g10
        float gBz =  cp * ct, gBw =  sp * ct;   // g11

        const int mask = 8 >> (step & 3);
        #pragma unroll
        for (int i = 0; i < 16; i++) {
            if (i & mask) continue;
            const int j = i | mask;
            float ar = re[i], ai = im[i], br = re[j], bi = im[j];
            re[i] = gAx * ar - gAy * ai + gAz * br - gAw * bi;
            im[i] = gAx * ai + gAy * ar + gAz * bi + gAw * br;
            re[j] = gBx * ar - gBy * ai + gBz * br - gBw * bi;
            im[j] = gBx * ai + gBy * ar + gBz * bi + gBw * br;
        }
        if ((step & 3) == 3) {
            float tr[16], ti[16];
            #pragma unroll
            for (int x = 0; x < 16; x++) { tr[PERM[x]] = re[x]; ti[PERM[x]] = im[x]; }
            #pragma unroll
            for (int x = 0; x < 16; x++) { re[x] = tr[x]; im[x] = ti[x]; }
        }
    }
    #pragma unroll
    for (int x = 0; x < 16; x++) { sur[ch][x][col] = re[x]; sui[ch][x][col] = im[x]; }
    __syncthreads();

    // M' rows: thread = (ch, i = col); entries j >= i; off-diag doubled here.
    {
        const int i = col;
        float uri[16], uii[16];
        #pragma unroll
        for (int x = 0; x < 16; x++) { uri[x] = sur[ch][x][i]; uii[x] = sui[ch][x][i]; }
        int e = i * 16 - (i * (i - 1)) / 2;
        for (int j = i; j < 16; j++, e++) {
            float acc = 0.f;
            #pragma unroll
            for (int x = 0; x < 8; x++)
                acc += uri[x] * sur[ch][x][j] + uii[x] * sui[ch][x][j];
            #pragma unroll
            for (int x = 8; x < 16; x++)
                acc -= uri[x] * sur[ch][x][j] + uii[x] * sui[ch][x][j];
            if (j != i) acc += acc;          // fold the 2x
            g_M[e * M_CH + m] = acc;
        }
    }
}

// ---- Kernel P: streaming pool (byte-identical to proven 38us version). ----
__global__ __launch_bounds__(512) void pool_kernel(const float* __restrict__ in) {
    const int bid = blockIdx.x;            // 0..1023
    const int t   = threadIdx.x;           // 0..511
    const int b     = bid >> 3;
    const int slice = bid & (NSL - 1);
    const int rs    = t >> 7;
    const int m4    = t & 127;
    const int row   = slice * 4 + rs;

    const float4* rp = (const float4*)in
                     + ((size_t)b * 1024 + (size_t)row * 32) * 128 + m4;
    float4 sL = make_float4(0.f, 0.f, 0.f, 0.f);
    float4 sR = make_float4(0.f, 0.f, 0.f, 0.f);
    #pragma unroll
    for (int c = 0; c < 16; c++) {
        float4 v = __ldcs(rp + c * 128);
        sL.x += v.x; sL.y += v.y; sL.z += v.z; sL.w += v.w;
    }
    #pragma unroll
    for (int c = 16; c < 32; c++) {
        float4 v = __ldcs(rp + c * 128);
        sR.x += v.x; sR.y += v.y; sR.z += v.z; sR.w += v.w;
    }

    __shared__ float4 red[512 * 2];
    red[t * 2]     = sL;
    red[t * 2 + 1] = sR;
    __syncthreads();
    if (t < 256) {
        float4 a = red[t * 2],     b4 = red[(t + 256) * 2];
        float4 c = red[t * 2 + 1], d4 = red[(t + 256) * 2 + 1];
        a.x += b4.x; a.y += b4.y; a.z += b4.z; a.w += b4.w;
        c.x += d4.x; c.y += d4.y; c.z += d4.z; c.w += d4.w;
        red[t * 2]     = a;
        red[t * 2 + 1] = c;
    }
    __syncthreads();
    if (t < 128) {
        float4 a = red[t * 2],     b4 = red[(t + 128) * 2];
        float4 c = red[t * 2 + 1], d4 = red[(t + 128) * 2 + 1];
        a.x += b4.x; a.y += b4.y; a.z += b4.z; a.w += b4.w;
        c.x += d4.x; c.y += d4.y; c.z += d4.z; c.w += d4.w;
        float4* p = (float4*)g_part + ((size_t)(b * NSL + slice) * 2) * 128 + t;
        p[0]   = a;
        p[128] = c;
    }
}

__device__ __forceinline__ float fast_tanh(float x) {
    return __fdividef(2.f, 1.f + __expf(-2.f * x)) - 1.f;
}

// ---- Kernel Q: z = psi^T M' psi. CTA = (64-channel block) x (4 batches).
//      M-slice staged once in smem, reused by all 4 batches. ----
__global__ __launch_bounds__(256) void qf_kernel(float* __restrict__ out) {
    const int mblk = blockIdx.x & 7;       // 0..7  (8 x 64 channels)
    const int bblk = blockIdx.x >> 3;      // 0..31 (32 x 4 batches)
    const int t    = threadIdx.x;          // 0..255
    const int lb   = t >> 6;               // local batch 0..3
    const int lm   = t & 63;               // local channel 0..63
    const int b    = bblk * 4 + lb;
    const int m    = mblk * MBLK + lm;

    __shared__ float Msm[NPAIR][MBLK];     // 34.8 KB

    // stage the M-slice (coalesced; 34 iterations)
    #pragma unroll 4
    for (int k = t; k < NPAIR * MBLK; k += 256)
        Msm[k >> 6][k & 63] = g_M[(size_t)(k >> 6) * M_CH + mblk * MBLK + (k & 63)];

    // partials + psi while the staging loads are in flight
    const float* p = g_part + (size_t)b * (NSL * 2 * M_CH) + m;
    float v[16];
    #pragma unroll
    for (int s = 0; s < 16; s++) v[s] = p[s * M_CH];
    float a00 = 0.f, a01 = 0.f, a10 = 0.f, a11 = 0.f;
    #pragma unroll
    for (int s = 0; s < 4; s++) { a00 += v[s * 2]; a01 += v[s * 2 + 1]; }
    #pragma unroll
    for (int s = 4; s < 8; s++) { a10 += v[s * 2]; a11 += v[s * 2 + 1]; }

    const float PI = 3.14159265358979f;
    const float inv = 1.f / 256.f;
    float ang0 = fast_tanh(a00 * inv) * PI;
    float ang1 = fast_tanh(a01 * inv) * PI;
    float ang2 = fast_tanh(a10 * inv) * PI;
    float ang3 = fast_tanh(a11 * inv) * PI;

    float s0, c0, s1, c1, s2, c2, s3, c3;
    __sincosf(0.5f * ang0, &s0, &c0);
    __sincosf(0.5f * ang1, &s1, &c1);
    __sincosf(0.5f * ang2, &s2, &c2);
    __sincosf(0.5f * ang3, &s3, &c3);

    float psi[16];
    {
        float p0[2] = {c0, s0}, p1[2] = {c1, s1}, p2_[2] = {c2, s2}, p3[2] = {c3, s3};
        #pragma unroll
        for (int x = 0; x < 16; x++)
            psi[x] = p0[(x >> 3) & 1] * p1[(x >> 2) & 1] * p2_[(x >> 1) & 1] * p3[x & 1];
    }
    __syncthreads();

    // z = sum_e M'_e * psi_i * psi_j  (conflict-free LDS: lanes differ in lm)
    float z0 = 0.f, z1 = 0.f;
    int e = 0;
    #pragma unroll
    for (int i = 0; i < 16; i++) {
        const float pi_ = psi[i];
        #pragma unroll
        for (int j = i; j < 16; j++, e++) {
            float c = pi_ * psi[j];
            if (e & 1) z1 = fmaf(Msm[e][lm], c, z1);
            else       z0 = fmaf(Msm[e][lm], c, z0);
        }
    }
    out[(size_t)b * M_CH + m] = z0 + z1;
}

extern "C" void kernel_launch(void* const* d_in, const int* in_sizes, int n_in,
                              void* d_out, int out_size) {
    const float* in = (const float*)d_in[0];
    const float* w  = (const float*)d_in[1];
    if (n_in >= 2 && in_sizes[0] < in_sizes[1]) {
        const float* t = in; in = w; w = t;
    }
    mbuild_kernel<<<128, 64>>>(w);
    pool_kernel<<<B_SZ * NSL, 512>>>(in);
    qf_kernel<<<256, 256>>>((float*)d_out);
}

// round 12
// speedup vs baseline: 1.1852x; 1.1343x over previous
#include <cuda_runtime.h>
#include <math.h>

#define DEPTH 2
#define NQ 4
#define M_CH 512
#define B_SZ 128
#define NSL 8              // 4-row slices per image
#define NPAIR 136          // symmetric 16x16 pairs (x2 folded into off-diag)
#define MBLK 64            // channels per qf CTA
#define NMB 32             // mbuild CTAs (16 channels each)

// Pooling partials: [b][slice][side][m] -> 4 MB (L2-resident)
__device__ float g_part[B_SZ * NSL * 2 * M_CH];
// Quadratic-form matrices (2x folded off-diag), transposed: [pair e][m]
__device__ float g_M[NPAIR * M_CH];

// ---- Kernel F: CTAs 0..31 build M' (16 channels each, threads 0..255);
//      CTAs 32..1055 are the proven streaming pool. ----
__global__ __launch_bounds__(512, 2) void fused_kernel(const float* __restrict__ in,
                                                       const float* __restrict__ w) {
    const int bid = blockIdx.x;
    const int t   = threadIdx.x;

    __shared__ __align__(16) char smem_raw[34816];   // max(mbuild 34816, pool 16384)

    if (bid < NMB) {
        // ================= mbuild path (threads 0..255 active) =================
        if (t >= 256) return;
        float (*sur)[16][17] = (float (*)[16][17])smem_raw;                 // [16][16][17]
        float (*sui)[16][17] = (float (*)[16][17])(smem_raw + 17408);
        const int ch  = t >> 4;              // 0..15
        const int col = t & 15;              // basis column
        const int m   = bid * 16 + ch;

        float re[16], im[16];
        #pragma unroll
        for (int x = 0; x < 16; x++) { re[x] = (x == col) ? 1.f : 0.f; im[x] = 0.f; }

        const int PERM[16] = {0, 1, 3, 2, 6, 7, 5, 4, 12, 13, 15, 14, 10, 11, 9, 8};
        const float* wm = w + (size_t)m * (DEPTH * NQ * 3);

        #pragma unroll
        for (int step = 0; step < DEPTH * NQ; step++) {
            const float* wp = wm + step * 3;
            float phi = wp[0], th = wp[1], om = wp[2];
            float st, ct; __sincosf(0.5f * th,         &st, &ct);
            float sp, cp; __sincosf(0.5f * (phi + om), &sp, &cp);
            float sm, cm; __sincosf(0.5f * (phi - om), &sm, &cm);
            float gAx =  cp * ct, gAy = -sp * ct;
            float gAz = -cm * st, gAw = -sm * st;
            float gBx =  cm * st, gBy = -sm * st;
            float gBz =  cp * ct, gBw =  sp * ct;

            const int mask = 8 >> (step & 3);
            #pragma unroll
            for (int i = 0; i < 16; i++) {
                if (i & mask) continue;
                const int j = i | mask;
                float ar = re[i], ai = im[i], br = re[j], bi = im[j];
                re[i] = gAx * ar - gAy * ai + gAz * br - gAw * bi;
                im[i] = gAx * ai + gAy * ar + gAz * bi + gAw * br;
                re[j] = gBx * ar - gBy * ai + gBz * br - gBw * bi;
                im[j] = gBx * ai + gBy * ar + gBz * bi + gBw * br;
            }
            if ((step & 3) == 3) {
                float tr[16], ti[16];
                #pragma unroll
                for (int x = 0; x < 16; x++) { tr[PERM[x]] = re[x]; ti[PERM[x]] = im[x]; }
                #pragma unroll
                for (int x = 0; x < 16; x++) { re[x] = tr[x]; im[x] = ti[x]; }
            }
        }
        #pragma unroll
        for (int x = 0; x < 16; x++) { sur[ch][x][col] = re[x]; sui[ch][x][col] = im[x]; }
        __syncwarp();
        asm volatile("bar.sync 1, 256;" ::: "memory");

        // M' rows: thread = (ch, i = col); entries j >= i; off-diag doubled.
        {
            const int i = col;
            float uri[16], uii[16];
            #pragma unroll
            for (int x = 0; x < 16; x++) { uri[x] = sur[ch][x][i]; uii[x] = sui[ch][x][i]; }
            int e = i * 16 - (i * (i - 1)) / 2;
            for (int j = i; j < 16; j++, e++) {
                float acc = 0.f;
                #pragma unroll
                for (int x = 0; x < 8; x++)
                    acc += uri[x] * sur[ch][x][j] + uii[x] * sui[ch][x][j];
                #pragma unroll
                for (int x = 8; x < 16; x++)
                    acc -= uri[x] * sur[ch][x][j] + uii[x] * sui[ch][x][j];
                if (j != i) acc += acc;
                g_M[e * M_CH + m] = acc;
            }
        }
        return;
    }

    // ================= pool path (proven streaming body) =================
    float4* red = (float4*)smem_raw;       // [512*2]
    const int pbid  = bid - NMB;           // 0..1023
    const int b     = pbid >> 3;
    const int slice = pbid & (NSL - 1);
    const int rs    = t >> 7;
    const int m4    = t & 127;
    const int row   = slice * 4 + rs;

    const float4* rp = (const float4*)in
                     + ((size_t)b * 1024 + (size_t)row * 32) * 128 + m4;
    float4 sL = make_float4(0.f, 0.f, 0.f, 0.f);
    float4 sR = make_float4(0.f, 0.f, 0.f, 0.f);
    #pragma unroll
    for (int c = 0; c < 16; c++) {
        float4 v = __ldcs(rp + c * 128);
        sL.x += v.x; sL.y += v.y; sL.z += v.z; sL.w += v.w;
    }
    #pragma unroll
    for (int c = 16; c < 32; c++) {
        float4 v = __ldcs(rp + c * 128);
        sR.x += v.x; sR.y += v.y; sR.z += v.z; sR.w += v.w;
    }

    red[t * 2]     = sL;
    red[t * 2 + 1] = sR;
    __syncthreads();
    if (t < 256) {
        float4 a = red[t * 2],     b4 = red[(t + 256) * 2];
        float4 c = red[t * 2 + 1], d4 = red[(t + 256) * 2 + 1];
        a.x += b4.x; a.y += b4.y; a.z += b4.z; a.w += b4.w;
        c.x += d4.x; c.y += d4.y; c.z += d4.z; c.w += d4.w;
        red[t * 2]     = a;
        red[t * 2 + 1] = c;
    }
    __syncthreads();
    if (t < 128) {
        float4 a = red[t * 2],     b4 = red[(t + 128) * 2];
        float4 c = red[t * 2 + 1], d4 = red[(t + 128) * 2 + 1];
        a.x += b4.x; a.y += b4.y; a.z += b4.z; a.w += b4.w;
        c.x += d4.x; c.y += d4.y; c.z += d4.z; c.w += d4.w;
        float4* p = (float4*)g_part + ((size_t)(b * NSL + slice) * 2) * 128 + t;
        p[0]   = a;
        p[128] = c;
    }
}

__device__ __forceinline__ float fast_tanh(float x) {
    return __fdividef(2.f, 1.f + __expf(-2.f * x)) - 1.f;
}

// ---- Kernel Q: z = psi^T M' psi. CTA = (64-channel block) x (4 batches). ----
__global__ __launch_bounds__(256) void qf_kernel(float* __restrict__ out) {
    const int mblk = blockIdx.x & 7;       // 0..7
    const int bblk = blockIdx.x >> 3;      // 0..31
    const int t    = threadIdx.x;
    const int lb   = t >> 6;               // 0..3
    const int lm   = t & 63;               // 0..63
    const int b    = bblk * 4 + lb;
    const int m    = mblk * MBLK + lm;

    __shared__ float Msm[NPAIR][MBLK];     // 34.8 KB

    #pragma unroll 4
    for (int k = t; k < NPAIR * MBLK; k += 256)
        Msm[k >> 6][k & 63] = __ldg(&g_M[(size_t)(k >> 6) * M_CH + mblk * MBLK + (k & 63)]);

    const float* p = g_part + (size_t)b * (NSL * 2 * M_CH) + m;
    float v[16];
    #pragma unroll
    for (int s = 0; s < 16; s++) v[s] = p[s * M_CH];
    float a00 = 0.f, a01 = 0.f, a10 = 0.f, a11 = 0.f;
    #pragma unroll
    for (int s = 0; s < 4; s++) { a00 += v[s * 2]; a01 += v[s * 2 + 1]; }
    #pragma unroll
    for (int s = 4; s < 8; s++) { a10 += v[s * 2]; a11 += v[s * 2 + 1]; }

    const float PI = 3.14159265358979f;
    const float inv = 1.f / 256.f;
    float ang0 = fast_tanh(a00 * inv) * PI;
    float ang1 = fast_tanh(a01 * inv) * PI;
    float ang2 = fast_tanh(a10 * inv) * PI;
    float ang3 = fast_tanh(a11 * inv) * PI;

    float s0, c0, s1, c1, s2, c2, s3, c3;
    __sincosf(0.5f * ang0, &s0, &c0);
    __sincosf(0.5f * ang1, &s1, &c1);
    __sincosf(0.5f * ang2, &s2, &c2);
    __sincosf(0.5f * ang3, &s3, &c3);

    float psi[16];
    {
        float p0[2] = {c0, s0}, p1[2] = {c1, s1}, p2_[2] = {c2, s2}, p3[2] = {c3, s3};
        #pragma unroll
        for (int x = 0; x < 16; x++)
            psi[x] = p0[(x >> 3) & 1] * p1[(x >> 2) & 1] * p2_[(x >> 1) & 1] * p3[x & 1];
    }
    __syncthreads();

    float z0 = 0.f, z1 = 0.f, z2 = 0.f, z3 = 0.f;
    int e = 0;
    #pragma unroll
    for (int i = 0; i < 16; i++) {
        const float pi_ = psi[i];
        #pragma unroll
        for (int j = i; j < 16; j++, e++) {
            float c = pi_ * psi[j];
            switch (e & 3) {
                case 0: z0 = fmaf(Msm[e][lm], c, z0); break;
                case 1: z1 = fmaf(Msm[e][lm], c, z1); break;
                case 2: z2 = fmaf(Msm[e][lm], c, z2); break;
                default: z3 = fmaf(Msm[e][lm], c, z3); break;
            }
        }
    }
    out[(size_t)b * M_CH + m] = (z0 + z1) + (z2 + z3);
}

extern "C" void kernel_launch(void* const* d_in, const int* in_sizes, int n_in,
                              void* d_out, int out_size) {
    const float* in = (const float*)d_in[0];
    const float* w  = (const float*)d_in[1];
    if (n_in >= 2 && in_sizes[0] < in_sizes[1]) {
        const float* t = in; in = w; w = t;
    }
    fused_kernel<<<B_SZ * NSL + NMB, 512>>>(in, w);
    qf_kernel<<<256, 256>>>((float*)d_out);
}

// round 13
// speedup vs baseline: 1.2612x; 1.0641x over previous
#include <cuda_runtime.h>
#include <math.h>

#define DEPTH 2
#define NQ 4
#define M_CH 512
#define B_SZ 128
#define NSL 8              // 4-row slices per image
#define NPAIR 136          // symmetric 16x16 pairs (x2 folded into off-diag)
#define MBLK 64            // channels per qf CTA
#define NMB 32             // mbuild CTAs (16 channels each)

// Pooling partials: [b][slice][side][m] -> 2 MB (L2-resident)
__device__ float g_part[B_SZ * NSL * 2 * M_CH];
// Quadratic-form matrices (2x folded off-diag), transposed: [pair e][m]
__device__ float g_M[NPAIR * M_CH];

// ---- Kernel F: CTAs 0..31 build M' (16 channels each, threads 0..255);
//      CTAs 32..1055 are the proven streaming pool. (byte-identical to R12) ----
__global__ __launch_bounds__(512, 2) void fused_kernel(const float* __restrict__ in,
                                                       const float* __restrict__ w) {
    const int bid = blockIdx.x;
    const int t   = threadIdx.x;

    __shared__ __align__(16) char smem_raw[34816];

    if (bid < NMB) {
        // ================= mbuild path (threads 0..255 active) =================
        if (t >= 256) return;
        float (*sur)[16][17] = (float (*)[16][17])smem_raw;
        float (*sui)[16][17] = (float (*)[16][17])(smem_raw + 17408);
        const int ch  = t >> 4;
        const int col = t & 15;
        const int m   = bid * 16 + ch;

        float re[16], im[16];
        #pragma unroll
        for (int x = 0; x < 16; x++) { re[x] = (x == col) ? 1.f : 0.f; im[x] = 0.f; }

        const int PERM[16] = {0, 1, 3, 2, 6, 7, 5, 4, 12, 13, 15, 14, 10, 11, 9, 8};
        const float* wm = w + (size_t)m * (DEPTH * NQ * 3);

        #pragma unroll
        for (int step = 0; step < DEPTH * NQ; step++) {
            const float* wp = wm + step * 3;
            float phi = wp[0], th = wp[1], om = wp[2];
            float st, ct; __sincosf(0.5f * th,         &st, &ct);
            float sp, cp; __sincosf(0.5f * (phi + om), &sp, &cp);
            float sm, cm; __sincosf(0.5f * (phi - om), &sm, &cm);
            float gAx =  cp * ct, gAy = -sp * ct;
            float gAz = -cm * st, gAw = -sm * st;
            float gBx =  cm * st, gBy = -sm * st;
            float gBz =  cp * ct, gBw =  sp * ct;

            const int mask = 8 >> (step & 3);
            #pragma unroll
            for (int i = 0; i < 16; i++) {
                if (i & mask) continue;
                const int j = i | mask;
                float ar = re[i], ai = im[i], br = re[j], bi = im[j];
                re[i] = gAx * ar - gAy * ai + gAz * br - gAw * bi;
                im[i] = gAx * ai + gAy * ar + gAz * bi + gAw * br;
                re[j] = gBx * ar - gBy * ai + gBz * br - gBw * bi;
                im[j] = gBx * ai + gBy * ar + gBz * bi + gBw * br;
            }
            if ((step & 3) == 3) {
                float tr[16], ti[16];
                #pragma unroll
                for (int x = 0; x < 16; x++) { tr[PERM[x]] = re[x]; ti[PERM[x]] = im[x]; }
                #pragma unroll
                for (int x = 0; x < 16; x++) { re[x] = tr[x]; im[x] = ti[x]; }
            }
        }
        #pragma unroll
        for (int x = 0; x < 16; x++) { sur[ch][x][col] = re[x]; sui[ch][x][col] = im[x]; }
        __syncwarp();
        asm volatile("bar.sync 1, 256;" ::: "memory");

        {
            const int i = col;
            float uri[16], uii[16];
            #pragma unroll
            for (int x = 0; x < 16; x++) { uri[x] = sur[ch][x][i]; uii[x] = sui[ch][x][i]; }
            int e = i * 16 - (i * (i - 1)) / 2;
            for (int j = i; j < 16; j++, e++) {
                float acc = 0.f;
                #pragma unroll
                for (int x = 0; x < 8; x++)
                    acc += uri[x] * sur[ch][x][j] + uii[x] * sui[ch][x][j];
                #pragma unroll
                for (int x = 8; x < 16; x++)
                    acc -= uri[x] * sur[ch][x][j] + uii[x] * sui[ch][x][j];
                if (j != i) acc += acc;
                g_M[e * M_CH + m] = acc;
            }
        }
        return;
    }

    // ================= pool path (proven streaming body) =================
    float4* red = (float4*)smem_raw;
    const int pbid  = bid - NMB;
    const int b     = pbid >> 3;
    const int slice = pbid & (NSL - 1);
    const int rs    = t >> 7;
    const int m4    = t & 127;
    const int row   = slice * 4 + rs;

    const float4* rp = (const float4*)in
                     + ((size_t)b * 1024 + (size_t)row * 32) * 128 + m4;
    float4 sL = make_float4(0.f, 0.f, 0.f, 0.f);
    float4 sR = make_float4(0.f, 0.f, 0.f, 0.f);
    #pragma unroll
    for (int c = 0; c < 16; c++) {
        float4 v = __ldcs(rp + c * 128);
        sL.x += v.x; sL.y += v.y; sL.z += v.z; sL.w += v.w;
    }
    #pragma unroll
    for (int c = 16; c < 32; c++) {
        float4 v = __ldcs(rp + c * 128);
        sR.x += v.x; sR.y += v.y; sR.z += v.z; sR.w += v.w;
    }

    red[t * 2]     = sL;
    red[t * 2 + 1] = sR;
    __syncthreads();
    if (t < 256) {
        float4 a = red[t * 2],     b4 = red[(t + 256) * 2];
        float4 c = red[t * 2 + 1], d4 = red[(t + 256) * 2 + 1];
        a.x += b4.x; a.y += b4.y; a.z += b4.z; a.w += b4.w;
        c.x += d4.x; c.y += d4.y; c.z += d4.z; c.w += d4.w;
        red[t * 2]     = a;
        red[t * 2 + 1] = c;
    }
    __syncthreads();
    if (t < 128) {
        float4 a = red[t * 2],     b4 = red[(t + 128) * 2];
        float4 c = red[t * 2 + 1], d4 = red[(t + 128) * 2 + 1];
        a.x += b4.x; a.y += b4.y; a.z += b4.z; a.w += b4.w;
        c.x += d4.x; c.y += d4.y; c.z += d4.z; c.w += d4.w;
        float4* p = (float4*)g_part + ((size_t)(b * NSL + slice) * 2) * 128 + t;
        p[0]   = a;
        p[128] = c;
    }
}

__device__ __forceinline__ float fast_tanh(float x) {
    return __fdividef(2.f, 1.f + __expf(-2.f * x)) - 1.f;
}

// ---- Kernel Q v3: single wave. grid = 128 CTAs x 512 threads.
//      CTA = (64-channel block) x (8 batches); M-slice staged once (float4). ----
__global__ __launch_bounds__(512) void qf_kernel(float* __restrict__ out) {
    const int mblk = blockIdx.x & 7;       // 0..7   (8 x 64 channels)
    const int bblk = blockIdx.x >> 3;      // 0..15  (16 x 8 batches)
    const int t    = threadIdx.x;          // 0..511
    const int lb   = t >> 6;               // local batch 0..7
    const int lm   = t & 63;               // local channel 0..63
    const int b    = bblk * 8 + lb;
    const int m    = mblk * MBLK + lm;

    __shared__ float Msm[NPAIR][MBLK];     // 34.8 KB

    // stage the M-slice as float4: 2176 float4 over 512 threads (5 iters)
    {
        float4* dst = (float4*)&Msm[0][0];
        #pragma unroll
        for (int f = t; f < NPAIR * MBLK / 4; f += 512) {
            const int e   = f >> 4;            // pair row
            const int off = (f & 15) * 4;      // float offset in 64-wide slice
            dst[f] = *(const float4*)&g_M[(size_t)e * M_CH + mblk * MBLK + off];
        }
    }

    // partials + psi while staging loads are in flight
    const float* p = g_part + (size_t)b * (NSL * 2 * M_CH) + m;
    float v[16];
    #pragma unroll
    for (int s = 0; s < 16; s++) v[s] = p[s * M_CH];
    float a00 = 0.f, a01 = 0.f, a10 = 0.f, a11 = 0.f;
    #pragma unroll
    for (int s = 0; s < 4; s++) { a00 += v[s * 2]; a01 += v[s * 2 + 1]; }
    #pragma unroll
    for (int s = 4; s < 8; s++) { a10 += v[s * 2]; a11 += v[s * 2 + 1]; }

    const float PI = 3.14159265358979f;
    const float inv = 1.f / 256.f;
    float ang0 = fast_tanh(a00 * inv) * PI;
    float ang1 = fast_tanh(a01 * inv) * PI;
    float ang2 = fast_tanh(a10 * inv) * PI;
    float ang3 = fast_tanh(a11 * inv) * PI;

    float s0, c0, s1, c1, s2, c2, s3, c3;
    __sincosf(0.5f * ang0, &s0, &c0);
    __sincosf(0.5f * ang1, &s1, &c1);
    __sincosf(0.5f * ang2, &s2, &c2);
    __sincosf(0.5f * ang3, &s3, &c3);

    float psi[16];
    {
        float p0[2] = {c0, s0}, p1[2] = {c1, s1}, p2_[2] = {c2, s2}, p3[2] = {c3, s3};
        #pragma unroll
        for (int x = 0; x < 16; x++)
            psi[x] = p0[(x >> 3) & 1] * p1[(x >> 2) & 1] * p2_[(x >> 1) & 1] * p3[x & 1];
    }
    __syncthreads();

    // z = sum_e M'_e * psi_i * psi_j  (conflict-free LDS; 4 accumulators)
    float z0 = 0.f, z1 = 0.f, z2 = 0.f, z3 = 0.f;
    int e = 0;
    #pragma unroll
    for (int i = 0; i < 16; i++) {
        const float pi_ = psi[i];
        #pragma unroll
        for (int j = i; j < 16; j++, e++) {
            float c = pi_ * psi[j];
            switch (e & 3) {
                case 0: z0 = fmaf(Msm[e][lm], c, z0); break;
                case 1: z1 = fmaf(Msm[e][lm], c, z1); break;
                case 2: z2 = fmaf(Msm[e][lm], c, z2); break;
                default: z3 = fmaf(Msm[e][lm], c, z3); break;
            }
        }
    }
    out[(size_t)b * M_CH + m] = (z0 + z1) + (z2 + z3);
}

extern "C" void kernel_launch(void* const* d_in, const int* in_sizes, int n_in,
                              void* d_out, int out_size) {
    const float* in = (const float*)d_in[0];
    const float* w  = (const float*)d_in[1];
    if (n_in >= 2 && in_sizes[0] < in_sizes[1]) {
        const float* t = in; in = w; w = t;
    }
    fused_kernel<<<B_SZ * NSL + NMB, 512>>>(in, w);
    qf_kernel<<<128, 512>>>((float*)d_out);
}